// round 13
// baseline (speedup 1.0000x reference)
#include <cuda_runtime.h>
#include <cuda_fp16.h>
#include <math.h>
#include <stdint.h>

#define NN 50000
#define EE 1200000
#define GG 256
#define NBLK 196   // ceil(NN/256)

// ---------------- scratch ----------------------------------------------------
__device__ __half2 g_hx16[NN * 32];   // (x @ conv1_W) * dinv[n], fp16
__device__ float   g_h[NN * 64];      // running node features
__device__ __half2 g_u16[NN * 32];    // LN+PReLU output (fp16)
__device__ __half2 g_agg16[NN * 32];  // GEN aggregation output (fp16, MLP input)
__device__ float   g_xcat[NN * 256];  // JK concat buffer
__device__ int     g_hist[NN];
__device__ int     g_rowptr[NN + 1];  // consumed by scatter: ends as row-ENDS
__device__ int     g_colsrc[EE];
__device__ float   g_dinv[NN];
__device__ int     g_gstart[GG + 1];
__device__ __half  g_W1T[3 * 8192];   // W1^T fp16: [layer][o=128][k=64]
__device__ __half  g_W2T[3 * 8192];   // W2^T fp16: [layer][n=64][k=128]
__device__ int          g_blk_agg[NBLK];
__device__ int          g_blk_pref[NBLK];
__device__ volatile int g_blk_flag[NBLK];

__device__ __forceinline__ uint32_t smem_u32(const void* p) {
    uint32_t a;
    asm("{ .reg .u64 t; cvta.to.shared.u64 t, %1; cvt.u32.u64 %0, t; }" : "=r"(a) : "l"(p));
    return a;
}

// ---------------- fused setup: hist/flag zero + wprep + gstart ---------------
__global__ void k_setup(const int* __restrict__ batch,
                        const float* __restrict__ W1, const float* __restrict__ W2) {
    int i = blockIdx.x * 256 + threadIdx.x;
    if (i < NN) g_hist[i] = 0;
    if (i < NBLK) g_blk_flag[i] = 0;
    // weight prep: fp16 transposed
    if (i < 3 * 8192) {
        int l = i >> 13, r = i & 8191;
        int o = r >> 6, k = r & 63;
        g_W1T[i] = __float2half(W1[l * 8192 + k * 128 + o]);
    } else if (i < 6 * 8192) {
        int t = i - 3 * 8192;
        int l = t >> 13, r = t & 8191;
        int n = r >> 7, k = r & 127;
        g_W2T[t] = __float2half(W2[l * 8192 + k * 64 + n]);
    }
    // graph boundaries from sorted batch_idx
    if (i < NN) {
        int b = batch[i];
        int prev = (i == 0) ? -1 : batch[i - 1];
        for (int g = prev + 1; g <= b; g++) g_gstart[g] = i;
        if (i == NN - 1) {
            for (int g = b + 1; g <= GG; g++) g_gstart[g] = NN;
        }
    }
}

// ---------------- CSR build -------------------------------------------------
__global__ void k_hist(const int* __restrict__ dst) {
    int i = blockIdx.x * blockDim.x + threadIdx.x;
    if (i < EE) atomicAdd(&g_hist[dst[i]], 1);
}

__device__ __forceinline__ int wscan_incl32(int x, int lane) {
#pragma unroll
    for (int o = 1; o < 32; o <<= 1) {
        int y = __shfl_up_sync(0xffffffffu, x, o);
        if (lane >= o) x += y;
    }
    return x;
}

// single-launch decoupled-lookback scan: hist -> rowptr (+ dinv)
__global__ void k_scanlb() {
    __shared__ int wsum[8];
    __shared__ int sexc;
    int tid = threadIdx.x, bid = blockIdx.x;
    int lane = tid & 31, wid = tid >> 5;
    int i = bid * 256 + tid;
    int v = (i < NN) ? g_hist[i] : 0;
    int incl = wscan_incl32(v, lane);
    if (lane == 31) wsum[wid] = incl;
    __syncthreads();
    if (tid < 8) {
        int b = wsum[tid];
#pragma unroll
        for (int o = 1; o < 8; o <<= 1) {
            int y = __shfl_up_sync(0xffu, b, o);
            if (tid >= o) b += y;
        }
        wsum[tid] = b;
    }
    __syncthreads();
    int wbase = (wid > 0) ? wsum[wid - 1] : 0;
    int total = wsum[7];
    if (tid == 0) {
        if (bid == 0) {
            g_blk_pref[0] = total;
            __threadfence();
            g_blk_flag[0] = 2;
            sexc = 0;
        } else {
            g_blk_agg[bid] = total;
            __threadfence();
            g_blk_flag[bid] = 1;
        }
    }
    if (bid > 0 && wid == 0) {
        int run = 0;
        int p = bid - 1;
        while (true) {
            int idx = p - lane;
            int f = 0, a = 0;
            if (idx >= 0) {
                while ((f = g_blk_flag[idx]) == 0) {}
                __threadfence();
                a = (f == 2) ? g_blk_pref[idx] : g_blk_agg[idx];
            }
            unsigned pm = __ballot_sync(0xffffffffu, idx >= 0 && f == 2);
            if (pm) {
                int stop = __ffs(pm) - 1;
                int take = (idx >= 0 && lane <= stop) ? a : 0;
#pragma unroll
                for (int o = 16; o > 0; o >>= 1) take += __shfl_xor_sync(0xffffffffu, take, o);
                run += take;
                break;
            } else {
                int take = (idx >= 0) ? a : 0;
#pragma unroll
                for (int o = 16; o > 0; o >>= 1) take += __shfl_xor_sync(0xffffffffu, take, o);
                run += take;
                p -= 32;
            }
        }
        if (lane == 0) {
            sexc = run;
            g_blk_pref[bid] = run + total;
            __threadfence();
            g_blk_flag[bid] = 2;
        }
    }
    __syncthreads();
    if (i < NN) {
        g_rowptr[i] = sexc + wbase + incl - v;
        g_dinv[i] = rsqrtf((float)(v + 1));
    }
}

// scatter consumes rowptr; 2 edges per thread for MLP
__global__ void k_scatter(const int* __restrict__ src, const int* __restrict__ dst) {
    const int HALF = EE / 2;
    int i = blockIdx.x * blockDim.x + threadIdx.x;
    if (i < HALF) {
        int d0 = __ldg(&dst[i]);
        int d1 = __ldg(&dst[i + HALF]);
        int s0 = __ldg(&src[i]);
        int s1 = __ldg(&src[i + HALF]);
        int p0 = atomicAdd(&g_rowptr[d0], 1);
        int p1 = atomicAdd(&g_rowptr[d1], 1);
        g_colsrc[p0] = s0;
        g_colsrc[p1] = s1;
    }
}

// ---------------- x @ conv1_W, pre-scaled by dinv[n]; fp16 only --------------
__global__ void k_hx(const float* __restrict__ x, const float* __restrict__ W) {
    int idx = blockIdx.x * blockDim.x + threadIdx.x;
    if (idx >= NN * 32) return;
    int n = idx >> 5, p = idx & 31;
    float a0 = 0.f, a1 = 0.f;
#pragma unroll
    for (int f = 0; f < 5; f++) {
        float xv = x[n * 5 + f];
        a0 += xv * W[f * 64 + 2 * p];
        a1 += xv * W[f * 64 + 2 * p + 1];
    }
    float dn = g_dinv[n];
    g_hx16[n * 32 + p] = __floats2half2_rn(a0 * dn, a1 * dn);
}

// ---- GCNConv aggregate + BN + ReLU + fused layer-0 LN+PReLU -----------------
__global__ void k_gcn(const float* __restrict__ cb, const float* __restrict__ bg,
                      const float* __restrict__ bb, const float* __restrict__ lg,
                      const float* __restrict__ lb, const float* __restrict__ pa) {
    int tid = threadIdx.x;
    int n = blockIdx.x * 8 + (tid >> 5);
    int l = tid & 31;
    if (n >= NN) return;
    int b = (n == 0) ? 0 : g_rowptr[n - 1];
    int e = g_rowptr[n];
    float a0 = 0.f, a1 = 0.f;
    int i = b;
    for (; i + 8 <= e; i += 8) {
        int s0 = g_colsrc[i], s1 = g_colsrc[i + 1];
        int s2 = g_colsrc[i + 2], s3 = g_colsrc[i + 3];
        int s4 = g_colsrc[i + 4], s5 = g_colsrc[i + 5];
        int s6 = g_colsrc[i + 6], s7 = g_colsrc[i + 7];
        float2 f0 = __half22float2(g_hx16[s0 * 32 + l]);
        float2 f1 = __half22float2(g_hx16[s1 * 32 + l]);
        float2 f2 = __half22float2(g_hx16[s2 * 32 + l]);
        float2 f3 = __half22float2(g_hx16[s3 * 32 + l]);
        float2 f4 = __half22float2(g_hx16[s4 * 32 + l]);
        float2 f5 = __half22float2(g_hx16[s5 * 32 + l]);
        float2 f6 = __half22float2(g_hx16[s6 * 32 + l]);
        float2 f7 = __half22float2(g_hx16[s7 * 32 + l]);
        a0 += ((f0.x + f1.x) + (f2.x + f3.x)) + ((f4.x + f5.x) + (f6.x + f7.x));
        a1 += ((f0.y + f1.y) + (f2.y + f3.y)) + ((f4.y + f5.y) + (f6.y + f7.y));
    }
    for (; i < e; i++) {
        float2 f = __half22float2(g_hx16[g_colsrc[i] * 32 + l]);
        a0 += f.x;
        a1 += f.y;
    }
    float2 hx = __half22float2(g_hx16[n * 32 + l]);
    float dn = g_dinv[n];
    const float BNS = rsqrtf(1.f + 1e-5f);
    float v0 = (a0 + hx.x) * dn + cb[2 * l];
    float v1 = (a1 + hx.y) * dn + cb[2 * l + 1];
    v0 = fmaxf(v0 * (bg[2 * l] * BNS) + bb[2 * l], 0.f);
    v1 = fmaxf(v1 * (bg[2 * l + 1] * BNS) + bb[2 * l + 1], 0.f);
    float2 o; o.x = v0; o.y = v1;
    *reinterpret_cast<float2*>(&g_h[n * 64 + 2 * l]) = o;
    *reinterpret_cast<float2*>(&g_xcat[n * 256 + 2 * l]) = o;
    // fused layer-0 LayerNorm + PReLU -> u16
    float s = v0 + v1;
    float q = v0 * v0 + v1 * v1;
#pragma unroll
    for (int off = 16; off > 0; off >>= 1) {
        s += __shfl_xor_sync(0xffffffffu, s, off);
        q += __shfl_xor_sync(0xffffffffu, q, off);
    }
    float mu = s * (1.f / 64.f);
    float var = q * (1.f / 64.f) - mu * mu;
    float rs = rsqrtf(var + 1e-5f);
    float y0 = (v0 - mu) * rs * lg[2 * l] + lb[2 * l];
    y0 = (y0 >= 0.f) ? y0 : pa[2 * l] * y0;
    float y1 = (v1 - mu) * rs * lg[2 * l + 1] + lb[2 * l + 1];
    y1 = (y1 >= 0.f) ? y1 : pa[2 * l + 1] * y1;
    g_u16[n * 32 + l] = __floats2half2_rn(y0, y1);
}

// ---------------- LayerNorm + PReLU (layers 1,2): h -> u16 only --------------
__global__ void k_ln(const float* __restrict__ g, const float* __restrict__ b,
                     const float* __restrict__ a) {
    int tid = threadIdx.x;
    int n = blockIdx.x * 8 + (tid >> 5);
    int l = tid & 31;
    if (n >= NN) return;
    float2 v = *reinterpret_cast<const float2*>(&g_h[n * 64 + 2 * l]);
    float s = v.x + v.y;
    float q = v.x * v.x + v.y * v.y;
#pragma unroll
    for (int off = 16; off > 0; off >>= 1) {
        s += __shfl_xor_sync(0xffffffffu, s, off);
        q += __shfl_xor_sync(0xffffffffu, q, off);
    }
    float mu = s * (1.f / 64.f);
    float var = q * (1.f / 64.f) - mu * mu;
    float rs = rsqrtf(var + 1e-5f);
    float y0 = (v.x - mu) * rs * g[2 * l] + b[2 * l];
    y0 = (y0 >= 0.f) ? y0 : a[2 * l] * y0;
    float y1 = (v.y - mu) * rs * g[2 * l + 1] + b[2 * l + 1];
    y1 = (y1 >= 0.f) ? y1 : a[2 * l + 1] * y1;
    g_u16[n * 32 + l] = __floats2half2_rn(y0, y1);
}

// ---------------- GENConv softmax aggregation (warp per node, fp16) ----------
__global__ void k_gen(const float* __restrict__ gen_t, int layer) {
    int tid = threadIdx.x;
    int n = blockIdx.x * 8 + (tid >> 5);
    int l = tid & 31;
    if (n >= NN) return;
    float t = __ldg(&gen_t[layer]);
    int b = (n == 0) ? 0 : g_rowptr[n - 1];
    int e = g_rowptr[n];
    float s0 = 0.f, s1 = 0.f, ac0 = 0.f, ac1 = 0.f;
    int i = b;
    for (; i + 8 <= e; i += 8) {
#pragma unroll
        for (int z = 0; z < 8; z += 4) {
            int sA = g_colsrc[i + z], sB = g_colsrc[i + z + 1];
            int sC = g_colsrc[i + z + 2], sD = g_colsrc[i + z + 3];
            float2 fA = __half22float2(g_u16[sA * 32 + l]);
            float2 fB = __half22float2(g_u16[sB * 32 + l]);
            float2 fC = __half22float2(g_u16[sC * 32 + l]);
            float2 fD = __half22float2(g_u16[sD * 32 + l]);
            float vA0 = fmaxf(fA.x, 0.f) + 1e-7f, vA1 = fmaxf(fA.y, 0.f) + 1e-7f;
            float vB0 = fmaxf(fB.x, 0.f) + 1e-7f, vB1 = fmaxf(fB.y, 0.f) + 1e-7f;
            float vC0 = fmaxf(fC.x, 0.f) + 1e-7f, vC1 = fmaxf(fC.y, 0.f) + 1e-7f;
            float vD0 = fmaxf(fD.x, 0.f) + 1e-7f, vD1 = fmaxf(fD.y, 0.f) + 1e-7f;
            float eA0 = __expf(vA0 * t), eA1 = __expf(vA1 * t);
            float eB0 = __expf(vB0 * t), eB1 = __expf(vB1 * t);
            float eC0 = __expf(vC0 * t), eC1 = __expf(vC1 * t);
            float eD0 = __expf(vD0 * t), eD1 = __expf(vD1 * t);
            s0 += (eA0 + eB0) + (eC0 + eD0);
            s1 += (eA1 + eB1) + (eC1 + eD1);
            ac0 += (vA0 * eA0 + vB0 * eB0) + (vC0 * eC0 + vD0 * eD0);
            ac1 += (vA1 * eA1 + vB1 * eB1) + (vC1 * eC1 + vD1 * eD1);
        }
    }
    for (; i < e; i++) {
        float2 f = __half22float2(g_u16[g_colsrc[i] * 32 + l]);
        float v0 = fmaxf(f.x, 0.f) + 1e-7f;
        float v1 = fmaxf(f.y, 0.f) + 1e-7f;
        float e0 = __expf(v0 * t), e1 = __expf(v1 * t);
        s0 += e0; s1 += e1;
        ac0 += v0 * e0; ac1 += v1 * e1;
    }
    float2 u = __half22float2(g_u16[n * 32 + l]);
    float o0 = ((e > b) ? (ac0 / s0) : 0.f) + u.x;
    float o1 = ((e > b) ? (ac1 / s1) : 0.f) + u.y;
    g_agg16[n * 32 + l] = __floats2half2_rn(o0, o1);
}

// ---------------- HMMA fused MLP (R8 version) --------------------------------
#define STA 72    // halves per A row (144B)
#define STW2 136  // halves per W2 row (272B)

__device__ __forceinline__ void ldmx4(uint32_t addr, uint32_t& a0, uint32_t& a1,
                                      uint32_t& a2, uint32_t& a3) {
    asm volatile("ldmatrix.sync.aligned.m8n8.x4.shared.b16 {%0,%1,%2,%3}, [%4];"
                 : "=r"(a0), "=r"(a1), "=r"(a2), "=r"(a3) : "r"(addr));
}
__device__ __forceinline__ void ldmx2(uint32_t addr, uint32_t& b0, uint32_t& b1) {
    asm volatile("ldmatrix.sync.aligned.m8n8.x2.shared.b16 {%0,%1}, [%2];"
                 : "=r"(b0), "=r"(b1) : "r"(addr));
}
__device__ __forceinline__ void mma16816(float* c, const uint32_t* a, const uint32_t* b) {
    asm volatile("mma.sync.aligned.m16n8k16.row.col.f32.f16.f16.f32 "
                 "{%0,%1,%2,%3}, {%4,%5,%6,%7}, {%8,%9}, {%0,%1,%2,%3};"
                 : "+f"(c[0]), "+f"(c[1]), "+f"(c[2]), "+f"(c[3])
                 : "r"(a[0]), "r"(a[1]), "r"(a[2]), "r"(a[3]), "r"(b[0]), "r"(b[1]));
}

__global__ void __launch_bounds__(256)
k_mma(const float* __restrict__ b1, const float* __restrict__ bng,
      const float* __restrict__ bnb, const float* __restrict__ b2, int layer) {
    extern __shared__ char smem[];
    float*  mpar = (float*)smem;              // 128
    float*  apar = mpar + 128;                // 128
    __half* sA   = (__half*)(apar + 128);     // 128*STA
    __half* sW1  = sA + 128 * STA;            // 128*STA
    __half* sW2  = sW1 + 128 * STA;           // 64*STW2
    int tid = threadIdx.x;
    int n0 = blockIdx.x * 128;

    if (tid < 128) {
        const float BNS = rsqrtf(1.f + 1e-5f);
        float m = __ldg(&bng[tid]) * BNS;
        mpar[tid] = m;
        apar[tid] = __ldg(&b1[tid]) * m + __ldg(&bnb[tid]);
    }
    for (int i = tid; i < 128 * 32; i += 256) {
        int r = i >> 5, p = i & 31;
        int n = n0 + r;
        __half2 v = (n < NN) ? g_agg16[n * 32 + p] : __floats2half2_rn(0.f, 0.f);
        *(__half2*)&sA[r * STA + 2 * p] = v;
    }
    const __half* w1p = g_W1T + layer * 8192;
    for (int i = tid; i < 128 * 32; i += 256) {
        int r = i >> 5, p = i & 31;
        *(__half2*)&sW1[r * STA + 2 * p] = *(const __half2*)&w1p[r * 64 + 2 * p];
    }
    const __half* w2p = g_W2T + layer * 8192;
    for (int i = tid; i < 64 * 64; i += 256) {
        int r = i >> 6, p = i & 63;
        *(__half2*)&sW2[r * STW2 + 2 * p] = *(const __half2*)&w2p[r * 128 + 2 * p];
    }
    __syncthreads();

    int wid = tid >> 5, lane = tid & 31;
    int m0 = wid * 16;

    float c[16][4];
#pragma unroll
    for (int nt = 0; nt < 16; nt++)
#pragma unroll
        for (int q = 0; q < 4; q++) c[nt][q] = 0.f;

    int arow = m0 + (lane & 7) + ((lane >> 3) & 1) * 8;
    int acolbase = (lane >> 4) * 8;
    int brow = (lane & 7);
    int bcolbase = ((lane >> 3) & 1) * 8;
#pragma unroll
    for (int kt = 0; kt < 4; kt++) {
        uint32_t a[4];
        ldmx4(smem_u32(&sA[arow * STA + kt * 16 + acolbase]), a[0], a[1], a[2], a[3]);
#pragma unroll
        for (int nt = 0; nt < 16; nt++) {
            uint32_t b[2];
            ldmx2(smem_u32(&sW1[(nt * 8 + brow) * STA + kt * 16 + bcolbase]), b[0], b[1]);
            mma16816(c[nt], a, b);
        }
    }

    int ob = (lane & 3) * 2;
    uint32_t az[8][4];
#pragma unroll
    for (int nt = 0; nt < 16; nt++) {
        int o0 = nt * 8 + ob, o1 = o0 + 1;
        float m0f = mpar[o0], m1f = mpar[o1];
        float a0f = apar[o0], a1f = apar[o1];
        float z0 = fmaxf(c[nt][0] * m0f + a0f, 0.f);
        float z1 = fmaxf(c[nt][1] * m1f + a1f, 0.f);
        float z2 = fmaxf(c[nt][2] * m0f + a0f, 0.f);
        float z3 = fmaxf(c[nt][3] * m1f + a1f, 0.f);
        __half2 p01 = __floats2half2_rn(z0, z1);
        __half2 p23 = __floats2half2_rn(z2, z3);
        az[nt >> 1][(nt & 1) * 2 + 0] = *(uint32_t*)&p01;
        az[nt >> 1][(nt & 1) * 2 + 1] = *(uint32_t*)&p23;
    }

    float d[8][4];
#pragma unroll
    for (int nt = 0; nt < 8; nt++)
#pragma unroll
        for (int q = 0; q < 4; q++) d[nt][q] = 0.f;
#pragma unroll
    for (int kt = 0; kt < 8; kt++) {
#pragma unroll
        for (int nt = 0; nt < 8; nt++) {
            uint32_t b[2];
            ldmx2(smem_u32(&sW2[(nt * 8 + brow) * STW2 + kt * 16 + bcolbase]), b[0], b[1]);
            mma16816(d[nt], az[kt], b);
        }
    }

    int r0 = n0 + m0 + (lane >> 2);
    int r1 = r0 + 8;
    int xoff = (layer + 1) * 64;
#pragma unroll
    for (int nt = 0; nt < 8; nt++) {
        int o0 = nt * 8 + ob;
        float bb0 = __ldg(&b2[o0]);
        float bb1 = __ldg(&b2[o0 + 1]);
        if (r0 < NN) {
            float2 hv = *(float2*)&g_h[r0 * 64 + o0];
            float2 nh;
            nh.x = hv.x + d[nt][0] + bb0;
            nh.y = hv.y + d[nt][1] + bb1;
            *(float2*)&g_h[r0 * 64 + o0] = nh;
            *(float2*)&g_xcat[r0 * 256 + xoff + o0] = nh;
        }
        if (r1 < NN) {
            float2 hv = *(float2*)&g_h[r1 * 64 + o0];
            float2 nh;
            nh.x = hv.x + d[nt][2] + bb0;
            nh.y = hv.y + d[nt][3] + bb1;
            *(float2*)&g_h[r1 * 64 + o0] = nh;
            *(float2*)&g_xcat[r1 * 256 + xoff + o0] = nh;
        }
    }
}
#define MMA_SMEM (256 * 4 + (128 * STA + 128 * STA + 64 * STW2) * 2)

// ---------------- fused pooling + readout MLP (512 threads) ------------------
__global__ void k_poolread(const float* __restrict__ W1, const float* __restrict__ b1,
                           const float* __restrict__ W2, const float* __restrict__ b2,
                           const float* __restrict__ Wo, const float* __restrict__ bo,
                           float* __restrict__ out) {
    __shared__ float ps[512];
    __shared__ float pm[512];
    __shared__ float p[512];
    __shared__ float q1[128];
    __shared__ float q2[64];
    int g = blockIdx.x;
    int tid = threadIdx.x;   // 512
    int c = tid & 255, half = tid >> 8;
    int beg = g_gstart[g], end = g_gstart[g + 1];
    float sum = 0.f, mx = -INFINITY;
    for (int n = beg + half; n < end; n += 2) {
        float v = g_xcat[n * 256 + c];
        sum += v;
        mx = fmaxf(mx, v);
    }
    ps[tid] = sum;
    pm[tid] = mx;
    __syncthreads();
    if (tid < 256) {
        float s = ps[tid] + ps[tid + 256];
        float m = fmaxf(pm[tid], pm[tid + 256]);
        float cnt = (float)(end - beg);
        p[tid] = s / fmaxf(cnt, 1.f);
        p[256 + tid] = (end > beg) ? m : 0.f;
    }
    __syncthreads();
    if (tid < 128) {
        float a = b1[tid];
        for (int k = 0; k < 512; k++) a += p[k] * W1[k * 128 + tid];
        q1[tid] = fmaxf(a, 0.f);
    }
    __syncthreads();
    if (tid < 64) {
        float a = b2[tid];
        for (int k = 0; k < 128; k++) a += q1[k] * W2[k * 64 + tid];
        q2[tid] = fmaxf(a, 0.f);
    }
    __syncthreads();
    if (tid < 32) {
        float s = q2[tid] * Wo[tid] + q2[tid + 32] * Wo[tid + 32];
#pragma unroll
        for (int off = 16; off > 0; off >>= 1) s += __shfl_xor_sync(0xffffffffu, s, off);
        if (tid == 0) out[g] = s + bo[0];
    }
}

// ---------------- launch -----------------------------------------------------
extern "C" void kernel_launch(void* const* d_in, const int* in_sizes, int n_in,
                              void* d_out, int out_size) {
    const float* x        = (const float*)d_in[0];
    const int*   ei       = (const int*)d_in[1];
    const int*   batch    = (const int*)d_in[2];
    const float* conv1_W  = (const float*)d_in[3];
    const float* conv1_b  = (const float*)d_in[4];
    const float* bn1_g    = (const float*)d_in[5];
    const float* bn1_b    = (const float*)d_in[6];
    const float* ln_g     = (const float*)d_in[7];
    const float* ln_b     = (const float*)d_in[8];
    const float* prelu_a  = (const float*)d_in[9];
    const float* gen_t    = (const float*)d_in[10];
    const float* mlp_W1   = (const float*)d_in[11];
    const float* mlp_b1   = (const float*)d_in[12];
    const float* mlp_bn_g = (const float*)d_in[13];
    const float* mlp_bn_b = (const float*)d_in[14];
    const float* mlp_W2   = (const float*)d_in[15];
    const float* mlp_b2   = (const float*)d_in[16];
    const float* lin1_W   = (const float*)d_in[17];
    const float* lin1_b   = (const float*)d_in[18];
    const float* lin2_W   = (const float*)d_in[19];
    const float* lin2_b   = (const float*)d_in[20];
    const float* out_W    = (const float*)d_in[21];
    const float* out_b    = (const float*)d_in[22];
    float* out = (float*)d_out;

    const int* src = ei;
    const int* dst = ei + EE;

    static int smem_set = 0;
    if (!smem_set) {
        cudaFuncSetAttribute(k_mma, cudaFuncAttributeMaxDynamicSharedMemorySize, MMA_SMEM);
        smem_set = 1;
    }

    k_setup<<<NBLK, 256>>>(batch, mlp_W1, mlp_W2);
    k_hist<<<(EE + 255) / 256, 256>>>(dst);
    k_scanlb<<<NBLK, 256>>>();
    k_scatter<<<(EE / 2 + 255) / 256, 256>>>(src, dst);
    k_hx<<<(NN * 32 + 255) / 256, 256>>>(x, conv1_W);
    k_gcn<<<(NN + 7) / 8, 256>>>(conv1_b, bn1_g, bn1_b, ln_g, ln_b, prelu_a);

    for (int i = 0; i < 3; i++) {
        if (i > 0) k_ln<<<(NN + 7) / 8, 256>>>(ln_g + i * 64, ln_b + i * 64, prelu_a + i * 64);
        k_gen<<<(NN + 7) / 8, 256>>>(gen_t, i);
        k_mma<<<(NN + 127) / 128, 256, MMA_SMEM>>>(mlp_b1 + i * 128, mlp_bn_g + i * 128,
                                                   mlp_bn_b + i * 128, mlp_b2 + i * 64, i);
    }

    k_poolread<<<GG, 512>>>(lin1_W, lin1_b, lin2_W, lin2_b, out_W, out_b, out);
}

// round 14
// speedup vs baseline: 1.0383x; 1.0383x over previous
#include <cuda_runtime.h>
#include <cuda_fp16.h>
#include <math.h>
#include <stdint.h>

#define NN 50000
#define EE 1200000
#define GG 256
#define NBLK 196   // ceil(NN/256)

// ---------------- scratch (zero-initialized at module load) ------------------
__device__ __half2 g_hx16[NN * 32];   // (x @ conv1_W) * dinv[n], fp16
__device__ float   g_h[NN * 64];      // running node features (fp32)
__device__ __half2 g_u16[NN * 32];    // LN+PReLU output (fp16)
__device__ __half2 g_agg16[NN * 32];  // GEN aggregation output (fp16)
__device__ __half2 g_x16[NN * 128];   // JK concat buffer (fp16, 256 ch = 128 pairs)
__device__ int     g_hist[NN];        // INVARIANT: zero at kernel_launch entry
__device__ int     g_rowptr[NN + 1];  // consumed by scatter: ends as row-ENDS
__device__ int     g_colsrc[EE];
__device__ float   g_dinv[NN];
__device__ int     g_gstart[GG + 1];
__device__ __half  g_W1T[3 * 8192];   // W1^T fp16: [layer][o=128][k=64]
__device__ __half  g_W2T[3 * 8192];   // W2^T fp16: [layer][n=64][k=128]
__device__ int          g_blk_agg[NBLK];
__device__ int          g_blk_pref[NBLK];
__device__ volatile int g_blk_flag[NBLK];  // INVARIANT: zero at entry (reset by scatter)

__device__ __forceinline__ uint32_t smem_u32(const void* p) {
    uint32_t a;
    asm("{ .reg .u64 t; cvta.to.shared.u64 t, %1; cvt.u32.u64 %0, t; }" : "=r"(a) : "l"(p));
    return a;
}

// ---------------- CSR histogram (hist is pre-zeroed by invariant) ------------
__global__ void k_hist(const int* __restrict__ dst) {
    int i = blockIdx.x * blockDim.x + threadIdx.x;
    if (i < EE) atomicAdd(&g_hist[dst[i]], 1);
}

__device__ __forceinline__ int wscan_incl32(int x, int lane) {
#pragma unroll
    for (int o = 1; o < 32; o <<= 1) {
        int y = __shfl_up_sync(0xffffffffu, x, o);
        if (lane >= o) x += y;
    }
    return x;
}

// ---- mega-kernel: blocks 0..195  = lookback scan -> rowptr,dinv ; zero hist ;
//                                    fused hx (x@W scaled, fp16)
//      blocks 196..391 = weight prep + gstart ------------------------------
__global__ void k_scanall(const int* __restrict__ batch,
                          const float* __restrict__ x, const float* __restrict__ cw,
                          const float* __restrict__ W1, const float* __restrict__ W2) {
    int tid = threadIdx.x, bid = blockIdx.x;
    if (bid < NBLK) {
        __shared__ int wsum[8];
        __shared__ int sexc;
        int lane = tid & 31, wid = tid >> 5;
        int i = bid * 256 + tid;
        int v = (i < NN) ? g_hist[i] : 0;
        int incl = wscan_incl32(v, lane);
        if (lane == 31) wsum[wid] = incl;
        __syncthreads();
        if (tid < 8) {
            int b = wsum[tid];
#pragma unroll
            for (int o = 1; o < 8; o <<= 1) {
                int y = __shfl_up_sync(0xffu, b, o);
                if (tid >= o) b += y;
            }
            wsum[tid] = b;
        }
        __syncthreads();
        int wbase = (wid > 0) ? wsum[wid - 1] : 0;
        int total = wsum[7];
        if (tid == 0) {
            if (bid == 0) {
                g_blk_pref[0] = total;
                __threadfence();
                g_blk_flag[0] = 2;
                sexc = 0;
            } else {
                g_blk_agg[bid] = total;
                __threadfence();
                g_blk_flag[bid] = 1;
            }
        }
        if (bid > 0 && wid == 0) {
            int run = 0;
            int p = bid - 1;
            while (true) {
                int idx = p - lane;
                int f = 0, a = 0;
                if (idx >= 0) {
                    while ((f = g_blk_flag[idx]) == 0) {}
                    __threadfence();
                    a = (f == 2) ? g_blk_pref[idx] : g_blk_agg[idx];
                }
                unsigned pm = __ballot_sync(0xffffffffu, idx >= 0 && f == 2);
                if (pm) {
                    int stop = __ffs(pm) - 1;
                    int take = (idx >= 0 && lane <= stop) ? a : 0;
#pragma unroll
                    for (int o = 16; o > 0; o >>= 1) take += __shfl_xor_sync(0xffffffffu, take, o);
                    run += take;
                    break;
                } else {
                    int take = (idx >= 0) ? a : 0;
#pragma unroll
                    for (int o = 16; o > 0; o >>= 1) take += __shfl_xor_sync(0xffffffffu, take, o);
                    run += take;
                    p -= 32;
                }
            }
            if (lane == 0) {
                sexc = run;
                g_blk_pref[bid] = run + total;
                __threadfence();
                g_blk_flag[bid] = 2;
            }
        }
        __syncthreads();
        if (i < NN) {
            g_rowptr[i] = sexc + wbase + incl - v;
            g_dinv[i] = rsqrtf((float)(v + 1));
            g_hist[i] = 0;  // restore invariant for next run
        }
        __syncthreads();
        // fused hx for this block's 256 nodes (dinv local to block, now visible)
        int n0 = bid * 256;
        for (int j = tid; j < 256 * 32; j += 256) {
            int n = n0 + (j >> 5);
            if (n >= NN) break;
            int p = j & 31;
            float a0 = 0.f, a1 = 0.f;
#pragma unroll
            for (int f = 0; f < 5; f++) {
                float xv = x[n * 5 + f];
                a0 += xv * cw[f * 64 + 2 * p];
                a1 += xv * cw[f * 64 + 2 * p + 1];
            }
            float dn = g_dinv[n];
            g_hx16[n * 32 + p] = __floats2half2_rn(a0 * dn, a1 * dn);
        }
    } else {
        int i = (bid - NBLK) * 256 + tid;
        // weight prep: fp16 transposed
        if (i < 3 * 8192) {
            int l = i >> 13, r = i & 8191;
            int o = r >> 6, k = r & 63;
            g_W1T[i] = __float2half(W1[l * 8192 + k * 128 + o]);
        } else if (i < 6 * 8192) {
            int t = i - 3 * 8192;
            int l = t >> 13, r = t & 8191;
            int n = r >> 7, k = r & 127;
            g_W2T[t] = __float2half(W2[l * 8192 + k * 64 + n]);
        }
        // graph boundaries from sorted batch_idx
        if (i < NN) {
            int b = batch[i];
            int prev = (i == 0) ? -1 : batch[i - 1];
            for (int g = prev + 1; g <= b; g++) g_gstart[g] = i;
            if (i == NN - 1) {
                for (int g = b + 1; g <= GG; g++) g_gstart[g] = NN;
            }
        }
    }
}

// scatter consumes rowptr; also resets lookback flags for next run
__global__ void k_scatter(const int* __restrict__ src, const int* __restrict__ dst) {
    int i = blockIdx.x * blockDim.x + threadIdx.x;
    if (i < NBLK) g_blk_flag[i] = 0;
    if (i < EE) {
        int d = dst[i];
        int pos = atomicAdd(&g_rowptr[d], 1);
        g_colsrc[pos] = src[i];
    }
}

// ---- GCNConv aggregate + BN + ReLU + fused layer-0 LN+PReLU -----------------
__global__ void k_gcn(const float* __restrict__ cb, const float* __restrict__ bg,
                      const float* __restrict__ bb, const float* __restrict__ lg,
                      const float* __restrict__ lb, const float* __restrict__ pa) {
    int tid = threadIdx.x;
    int n = blockIdx.x * 8 + (tid >> 5);
    int l = tid & 31;
    if (n >= NN) return;
    int b = (n == 0) ? 0 : g_rowptr[n - 1];
    int e = g_rowptr[n];
    float a0 = 0.f, a1 = 0.f;
    int i = b;
    for (; i + 8 <= e; i += 8) {
        int s0 = g_colsrc[i], s1 = g_colsrc[i + 1];
        int s2 = g_colsrc[i + 2], s3 = g_colsrc[i + 3];
        int s4 = g_colsrc[i + 4], s5 = g_colsrc[i + 5];
        int s6 = g_colsrc[i + 6], s7 = g_colsrc[i + 7];
        float2 f0 = __half22float2(g_hx16[s0 * 32 + l]);
        float2 f1 = __half22float2(g_hx16[s1 * 32 + l]);
        float2 f2 = __half22float2(g_hx16[s2 * 32 + l]);
        float2 f3 = __half22float2(g_hx16[s3 * 32 + l]);
        float2 f4 = __half22float2(g_hx16[s4 * 32 + l]);
        float2 f5 = __half22float2(g_hx16[s5 * 32 + l]);
        float2 f6 = __half22float2(g_hx16[s6 * 32 + l]);
        float2 f7 = __half22float2(g_hx16[s7 * 32 + l]);
        a0 += ((f0.x + f1.x) + (f2.x + f3.x)) + ((f4.x + f5.x) + (f6.x + f7.x));
        a1 += ((f0.y + f1.y) + (f2.y + f3.y)) + ((f4.y + f5.y) + (f6.y + f7.y));
    }
    for (; i < e; i++) {
        float2 f = __half22float2(g_hx16[g_colsrc[i] * 32 + l]);
        a0 += f.x;
        a1 += f.y;
    }
    float2 hx = __half22float2(g_hx16[n * 32 + l]);
    float dn = g_dinv[n];
    const float BNS = rsqrtf(1.f + 1e-5f);
    float v0 = (a0 + hx.x) * dn + cb[2 * l];
    float v1 = (a1 + hx.y) * dn + cb[2 * l + 1];
    v0 = fmaxf(v0 * (bg[2 * l] * BNS) + bb[2 * l], 0.f);
    v1 = fmaxf(v1 * (bg[2 * l + 1] * BNS) + bb[2 * l + 1], 0.f);
    float2 o; o.x = v0; o.y = v1;
    *reinterpret_cast<float2*>(&g_h[n * 64 + 2 * l]) = o;
    g_x16[n * 128 + l] = __floats2half2_rn(v0, v1);
    // fused layer-0 LayerNorm + PReLU -> u16
    float s = v0 + v1;
    float q = v0 * v0 + v1 * v1;
#pragma unroll
    for (int off = 16; off > 0; off >>= 1) {
        s += __shfl_xor_sync(0xffffffffu, s, off);
        q += __shfl_xor_sync(0xffffffffu, q, off);
    }
    float mu = s * (1.f / 64.f);
    float var = q * (1.f / 64.f) - mu * mu;
    float rs = rsqrtf(var + 1e-5f);
    float y0 = (v0 - mu) * rs * lg[2 * l] + lb[2 * l];
    y0 = (y0 >= 0.f) ? y0 : pa[2 * l] * y0;
    float y1 = (v1 - mu) * rs * lg[2 * l + 1] + lb[2 * l + 1];
    y1 = (y1 >= 0.f) ? y1 : pa[2 * l + 1] * y1;
    g_u16[n * 32 + l] = __floats2half2_rn(y0, y1);
}

// ---------------- LayerNorm + PReLU (layers 1,2): h -> u16 only --------------
__global__ void k_ln(const float* __restrict__ g, const float* __restrict__ b,
                     const float* __restrict__ a) {
    int tid = threadIdx.x;
    int n = blockIdx.x * 8 + (tid >> 5);
    int l = tid & 31;
    if (n >= NN) return;
    float2 v = *reinterpret_cast<const float2*>(&g_h[n * 64 + 2 * l]);
    float s = v.x + v.y;
    float q = v.x * v.x + v.y * v.y;
#pragma unroll
    for (int off = 16; off > 0; off >>= 1) {
        s += __shfl_xor_sync(0xffffffffu, s, off);
        q += __shfl_xor_sync(0xffffffffu, q, off);
    }
    float mu = s * (1.f / 64.f);
    float var = q * (1.f / 64.f) - mu * mu;
    float rs = rsqrtf(var + 1e-5f);
    float y0 = (v.x - mu) * rs * g[2 * l] + b[2 * l];
    y0 = (y0 >= 0.f) ? y0 : a[2 * l] * y0;
    float y1 = (v.y - mu) * rs * g[2 * l + 1] + b[2 * l + 1];
    y1 = (y1 >= 0.f) ? y1 : a[2 * l + 1] * y1;
    g_u16[n * 32 + l] = __floats2half2_rn(y0, y1);
}

// ---------------- GENConv softmax aggregation (warp per node, fp16) ----------
__global__ void k_gen(const float* __restrict__ gen_t, int layer) {
    int tid = threadIdx.x;
    int n = blockIdx.x * 8 + (tid >> 5);
    int l = tid & 31;
    if (n >= NN) return;
    float t = __ldg(&gen_t[layer]);
    int b = (n == 0) ? 0 : g_rowptr[n - 1];
    int e = g_rowptr[n];
    float s0 = 0.f, s1 = 0.f, ac0 = 0.f, ac1 = 0.f;
    int i = b;
    for (; i + 8 <= e; i += 8) {
#pragma unroll
        for (int z = 0; z < 8; z += 4) {
            int sA = g_colsrc[i + z], sB = g_colsrc[i + z + 1];
            int sC = g_colsrc[i + z + 2], sD = g_colsrc[i + z + 3];
            float2 fA = __half22float2(g_u16[sA * 32 + l]);
            float2 fB = __half22float2(g_u16[sB * 32 + l]);
            float2 fC = __half22float2(g_u16[sC * 32 + l]);
            float2 fD = __half22float2(g_u16[sD * 32 + l]);
            float vA0 = fmaxf(fA.x, 0.f) + 1e-7f, vA1 = fmaxf(fA.y, 0.f) + 1e-7f;
            float vB0 = fmaxf(fB.x, 0.f) + 1e-7f, vB1 = fmaxf(fB.y, 0.f) + 1e-7f;
            float vC0 = fmaxf(fC.x, 0.f) + 1e-7f, vC1 = fmaxf(fC.y, 0.f) + 1e-7f;
            float vD0 = fmaxf(fD.x, 0.f) + 1e-7f, vD1 = fmaxf(fD.y, 0.f) + 1e-7f;
            float eA0 = __expf(vA0 * t), eA1 = __expf(vA1 * t);
            float eB0 = __expf(vB0 * t), eB1 = __expf(vB1 * t);
            float eC0 = __expf(vC0 * t), eC1 = __expf(vC1 * t);
            float eD0 = __expf(vD0 * t), eD1 = __expf(vD1 * t);
            s0 += (eA0 + eB0) + (eC0 + eD0);
            s1 += (eA1 + eB1) + (eC1 + eD1);
            ac0 += (vA0 * eA0 + vB0 * eB0) + (vC0 * eC0 + vD0 * eD0);
            ac1 += (vA1 * eA1 + vB1 * eB1) + (vC1 * eC1 + vD1 * eD1);
        }
    }
    for (; i < e; i++) {
        float2 f = __half22float2(g_u16[g_colsrc[i] * 32 + l]);
        float v0 = fmaxf(f.x, 0.f) + 1e-7f;
        float v1 = fmaxf(f.y, 0.f) + 1e-7f;
        float e0 = __expf(v0 * t), e1 = __expf(v1 * t);
        s0 += e0; s1 += e1;
        ac0 += v0 * e0; ac1 += v1 * e1;
    }
    float2 u = __half22float2(g_u16[n * 32 + l]);
    float o0 = ((e > b) ? (ac0 / s0) : 0.f) + u.x;
    float o1 = ((e > b) ? (ac1 / s1) : 0.f) + u.y;
    g_agg16[n * 32 + l] = __floats2half2_rn(o0, o1);
}

// ---------------- HMMA fused MLP (R8 math; xcat write now fp16) --------------
#define STA 72    // halves per A row (144B)
#define STW2 136  // halves per W2 row (272B)

__device__ __forceinline__ void ldmx4(uint32_t addr, uint32_t& a0, uint32_t& a1,
                                      uint32_t& a2, uint32_t& a3) {
    asm volatile("ldmatrix.sync.aligned.m8n8.x4.shared.b16 {%0,%1,%2,%3}, [%4];"
                 : "=r"(a0), "=r"(a1), "=r"(a2), "=r"(a3) : "r"(addr));
}
__device__ __forceinline__ void ldmx2(uint32_t addr, uint32_t& b0, uint32_t& b1) {
    asm volatile("ldmatrix.sync.aligned.m8n8.x2.shared.b16 {%0,%1}, [%2];"
                 : "=r"(b0), "=r"(b1) : "r"(addr));
}
__device__ __forceinline__ void mma16816(float* c, const uint32_t* a, const uint32_t* b) {
    asm volatile("mma.sync.aligned.m16n8k16.row.col.f32.f16.f16.f32 "
                 "{%0,%1,%2,%3}, {%4,%5,%6,%7}, {%8,%9}, {%0,%1,%2,%3};"
                 : "+f"(c[0]), "+f"(c[1]), "+f"(c[2]), "+f"(c[3])
                 : "r"(a[0]), "r"(a[1]), "r"(a[2]), "r"(a[3]), "r"(b[0]), "r"(b[1]));
}

__global__ void __launch_bounds__(256)
k_mma(const float* __restrict__ b1, const float* __restrict__ bng,
      const float* __restrict__ bnb, const float* __restrict__ b2, int layer) {
    extern __shared__ char smem[];
    float*  mpar = (float*)smem;              // 128
    float*  apar = mpar + 128;                // 128
    __half* sA   = (__half*)(apar + 128);     // 128*STA
    __half* sW1  = sA + 128 * STA;            // 128*STA
    __half* sW2  = sW1 + 128 * STA;           // 64*STW2
    int tid = threadIdx.x;
    int n0 = blockIdx.x * 128;

    if (tid < 128) {
        const float BNS = rsqrtf(1.f + 1e-5f);
        float m = __ldg(&bng[tid]) * BNS;
        mpar[tid] = m;
        apar[tid] = __ldg(&b1[tid]) * m + __ldg(&bnb[tid]);
    }
    for (int i = tid; i < 128 * 32; i += 256) {
        int r = i >> 5, p = i & 31;
        int n = n0 + r;
        __half2 v = (n < NN) ? g_agg16[n * 32 + p] : __floats2half2_rn(0.f, 0.f);
        *(__half2*)&sA[r * STA + 2 * p] = v;
    }
    const __half* w1p = g_W1T + layer * 8192;
    for (int i = tid; i < 128 * 32; i += 256) {
        int r = i >> 5, p = i & 31;
        *(__half2*)&sW1[r * STA + 2 * p] = *(const __half2*)&w1p[r * 64 + 2 * p];
    }
    const __half* w2p = g_W2T + layer * 8192;
    for (int i = tid; i < 64 * 64; i += 256) {
        int r = i >> 6, p = i & 63;
        *(__half2*)&sW2[r * STW2 + 2 * p] = *(const __half2*)&w2p[r * 128 + 2 * p];
    }
    __syncthreads();

    int wid = tid >> 5, lane = tid & 31;
    int m0 = wid * 16;

    float c[16][4];
#pragma unroll
    for (int nt = 0; nt < 16; nt++)
#pragma unroll
        for (int q = 0; q < 4; q++) c[nt][q] = 0.f;

    int arow = m0 + (lane & 7) + ((lane >> 3) & 1) * 8;
    int acolbase = (lane >> 4) * 8;
    int brow = (lane & 7);
    int bcolbase = ((lane >> 3) & 1) * 8;
#pragma unroll
    for (int kt = 0; kt < 4; kt++) {
        uint32_t a[4];
        ldmx4(smem_u32(&sA[arow * STA + kt * 16 + acolbase]), a[0], a[1], a[2], a[3]);
#pragma unroll
        for (int nt = 0; nt < 16; nt++) {
            uint32_t b[2];
            ldmx2(smem_u32(&sW1[(nt * 8 + brow) * STA + kt * 16 + bcolbase]), b[0], b[1]);
            mma16816(c[nt], a, b);
        }
    }

    int ob = (lane & 3) * 2;
    uint32_t az[8][4];
#pragma unroll
    for (int nt = 0; nt < 16; nt++) {
        int o0 = nt * 8 + ob, o1 = o0 + 1;
        float m0f = mpar[o0], m1f = mpar[o1];
        float a0f = apar[o0], a1f = apar[o1];
        float z0 = fmaxf(c[nt][0] * m0f + a0f, 0.f);
        float z1 = fmaxf(c[nt][1] * m1f + a1f, 0.f);
        float z2 = fmaxf(c[nt][2] * m0f + a0f, 0.f);
        float z3 = fmaxf(c[nt][3] * m1f + a1f, 0.f);
        __half2 p01 = __floats2half2_rn(z0, z1);
        __half2 p23 = __floats2half2_rn(z2, z3);
        az[nt >> 1][(nt & 1) * 2 + 0] = *(uint32_t*)&p01;
        az[nt >> 1][(nt & 1) * 2 + 1] = *(uint32_t*)&p23;
    }

    float d[8][4];
#pragma unroll
    for (int nt = 0; nt < 8; nt++)
#pragma unroll
        for (int q = 0; q < 4; q++) d[nt][q] = 0.f;
#pragma unroll
    for (int kt = 0; kt < 8; kt++) {
#pragma unroll
        for (int nt = 0; nt < 8; nt++) {
            uint32_t b[2];
            ldmx2(smem_u32(&sW2[(nt * 8 + brow) * STW2 + kt * 16 + bcolbase]), b[0], b[1]);
            mma16816(d[nt], az[kt], b);
        }
    }

    int r0 = n0 + m0 + (lane >> 2);
    int r1 = r0 + 8;
    int xoff = (layer + 1) * 32;   // pair offset in g_x16 row (128 pairs)
#pragma unroll
    for (int nt = 0; nt < 8; nt++) {
        int o0 = nt * 8 + ob;
        float bb0 = __ldg(&b2[o0]);
        float bb1 = __ldg(&b2[o0 + 1]);
        if (r0 < NN) {
            float2 hv = *(float2*)&g_h[r0 * 64 + o0];
            float2 nh;
            nh.x = hv.x + d[nt][0] + bb0;
            nh.y = hv.y + d[nt][1] + bb1;
            *(float2*)&g_h[r0 * 64 + o0] = nh;
            g_x16[r0 * 128 + xoff + (o0 >> 1)] = __floats2half2_rn(nh.x, nh.y);
        }
        if (r1 < NN) {
            float2 hv = *(float2*)&g_h[r1 * 64 + o0];
            float2 nh;
            nh.x = hv.x + d[nt][2] + bb0;
            nh.y = hv.y + d[nt][3] + bb1;
            *(float2*)&g_h[r1 * 64 + o0] = nh;
            g_x16[r1 * 128 + xoff + (o0 >> 1)] = __floats2half2_rn(nh.x, nh.y);
        }
    }
}
#define MMA_SMEM (256 * 4 + (128 * STA + 128 * STA + 64 * STW2) * 2)

// ---------------- fused pooling + readout MLP (512 thr, fp16 xcat) -----------
__global__ void k_poolread(const float* __restrict__ W1, const float* __restrict__ b1,
                           const float* __restrict__ W2, const float* __restrict__ b2,
                           const float* __restrict__ Wo, const float* __restrict__ bo,
                           float* __restrict__ out) {
    __shared__ float ss0[512], ss1[512], sm0[512], sm1[512];
    __shared__ float p[512];
    __shared__ float q1[128];
    __shared__ float q2[64];
    int g = blockIdx.x;
    int tid = threadIdx.x;        // 512
    int pc = tid & 127;           // channel pair 0..127
    int q4 = tid >> 7;            // node split 0..3
    int beg = g_gstart[g], end = g_gstart[g + 1];
    float s0 = 0.f, s1 = 0.f, m0 = -INFINITY, m1 = -INFINITY;
    for (int n = beg + q4; n < end; n += 4) {
        float2 v = __half22float2(g_x16[n * 128 + pc]);
        s0 += v.x; s1 += v.y;
        m0 = fmaxf(m0, v.x); m1 = fmaxf(m1, v.y);
    }
    ss0[tid] = s0; ss1[tid] = s1; sm0[tid] = m0; sm1[tid] = m1;
    __syncthreads();
    if (tid < 128) {
        float S0 = ss0[tid] + ss0[tid + 128] + ss0[tid + 256] + ss0[tid + 384];
        float S1 = ss1[tid] + ss1[tid + 128] + ss1[tid + 256] + ss1[tid + 384];
        float M0 = fmaxf(fmaxf(sm0[tid], sm0[tid + 128]), fmaxf(sm0[tid + 256], sm0[tid + 384]));
        float M1 = fmaxf(fmaxf(sm1[tid], sm1[tid + 128]), fmaxf(sm1[tid + 256], sm1[tid + 384]));
        float cnt = fmaxf((float)(end - beg), 1.f);
        p[2 * tid] = S0 / cnt;
        p[2 * tid + 1] = S1 / cnt;
        p[256 + 2 * tid] = (end > beg) ? M0 : 0.f;
        p[256 + 2 * tid + 1] = (end > beg) ? M1 : 0.f;
    }
    __syncthreads();
    if (tid < 128) {
        float a = b1[tid];
        for (int k = 0; k < 512; k++) a += p[k] * W1[k * 128 + tid];
        q1[tid] = fmaxf(a, 0.f);
    }
    __syncthreads();
    if (tid < 64) {
        float a = b2[tid];
        for (int k = 0; k < 128; k++) a += q1[k] * W2[k * 64 + tid];
        q2[tid] = fmaxf(a, 0.f);
    }
    __syncthreads();
    if (tid < 32) {
        float s = q2[tid] * Wo[tid] + q2[tid + 32] * Wo[tid + 32];
#pragma unroll
        for (int off = 16; off > 0; off >>= 1) s += __shfl_xor_sync(0xffffffffu, s, off);
        if (tid == 0) out[g] = s + bo[0];
    }
}

// ---------------- launch -----------------------------------------------------
extern "C" void kernel_launch(void* const* d_in, const int* in_sizes, int n_in,
                              void* d_out, int out_size) {
    const float* x        = (const float*)d_in[0];
    const int*   ei       = (const int*)d_in[1];
    const int*   batch    = (const int*)d_in[2];
    const float* conv1_W  = (const float*)d_in[3];
    const float* conv1_b  = (const float*)d_in[4];
    const float* bn1_g    = (const float*)d_in[5];
    const float* bn1_b    = (const float*)d_in[6];
    const float* ln_g     = (const float*)d_in[7];
    const float* ln_b     = (const float*)d_in[8];
    const float* prelu_a  = (const float*)d_in[9];
    const float* gen_t    = (const float*)d_in[10];
    const float* mlp_W1   = (const float*)d_in[11];
    const float* mlp_b1   = (const float*)d_in[12];
    const float* mlp_bn_g = (const float*)d_in[13];
    const float* mlp_bn_b = (const float*)d_in[14];
    const float* mlp_W2   = (const float*)d_in[15];
    const float* mlp_b2   = (const float*)d_in[16];
    const float* lin1_W   = (const float*)d_in[17];
    const float* lin1_b   = (const float*)d_in[18];
    const float* lin2_W   = (const float*)d_in[19];
    const float* lin2_b   = (const float*)d_in[20];
    const float* out_W    = (const float*)d_in[21];
    const float* out_b    = (const float*)d_in[22];
    float* out = (float*)d_out;

    const int* src = ei;
    const int* dst = ei + EE;

    static int smem_set = 0;
    if (!smem_set) {
        cudaFuncSetAttribute(k_mma, cudaFuncAttributeMaxDynamicSharedMemorySize, MMA_SMEM);
        smem_set = 1;
    }

    k_hist<<<(EE + 255) / 256, 256>>>(dst);
    k_scanall<<<2 * NBLK, 256>>>(batch, x, conv1_W, mlp_W1, mlp_W2);
    k_scatter<<<(EE + 255) / 256, 256>>>(src, dst);
    k_gcn<<<(NN + 7) / 8, 256>>>(conv1_b, bn1_g, bn1_b, ln_g, ln_b, prelu_a);

    for (int i = 0; i < 3; i++) {
        if (i > 0) k_ln<<<(NN + 7) / 8, 256>>>(ln_g + i * 64, ln_b + i * 64, prelu_a + i * 64);
        k_gen<<<(NN + 7) / 8, 256>>>(gen_t, i);
        k_mma<<<(NN + 127) / 128, 256, MMA_SMEM>>>(mlp_b1 + i * 128, mlp_bn_g + i * 128,
                                                   mlp_bn_b + i * 128, mlp_b2 + i * 64, i);
    }

    k_poolread<<<GG, 512>>>(lin1_W, lin1_b, lin2_W, lin2_b, out_W, out_b, out);
}

// round 17
// speedup vs baseline: 1.0576x; 1.0185x over previous
#include <cuda_runtime.h>
#include <cuda_fp16.h>
#include <math.h>
#include <stdint.h>

#define NN 50000
#define EE 1200000
#define GG 256
#define NBLK 196   // ceil(NN/256)

// ---------------- scratch (zero-initialized at module load) ------------------
__device__ __half2 g_hx16[NN * 32];   // (x @ conv1_W) * dinv[n], fp16
__device__ float   g_h[NN * 64];      // running node features (fp32)
__device__ __half2 g_u16[NN * 32];    // LN+PReLU output (fp16)
__device__ __half2 g_agg16[NN * 32];  // GEN aggregation output (fp16)
__device__ __half2 g_x16[NN * 128];   // JK concat buffer (fp16, 256 ch = 128 pairs)
__device__ int     g_hist[NN];        // INVARIANT: zero at kernel_launch entry
__device__ int     g_rowptr[NN + 1];  // consumed by scatter: ends as row-ENDS
__device__ int     g_colsrc[EE];      // stores src << 5 (pre-scaled row base)
__device__ float   g_dinv[NN];
__device__ int     g_gstart[GG + 1];
__device__ __half  g_W1T[3 * 8192];   // W1^T fp16: [layer][o=128][k=64]
__device__ __half  g_W2T[3 * 8192];   // W2^T fp16: [layer][n=64][k=128]
__device__ int          g_blk_agg[NBLK];
__device__ int          g_blk_pref[NBLK];
__device__ volatile int g_blk_flag[NBLK];  // INVARIANT: zero at entry (reset by scatter)

__device__ __forceinline__ uint32_t smem_u32(const void* p) {
    uint32_t a;
    asm("{ .reg .u64 t; cvta.to.shared.u64 t, %1; cvt.u32.u64 %0, t; }" : "=r"(a) : "l"(p));
    return a;
}

__device__ __forceinline__ float ex2f(float x) {
    float r;
    asm("ex2.approx.f32 %0, %1;" : "=f"(r) : "f"(x));
    return r;
}

// ---------------- CSR histogram ----------------------------------------------
__global__ void k_hist(const int* __restrict__ dst) {
    int i = blockIdx.x * blockDim.x + threadIdx.x;
    if (i < EE) atomicAdd(&g_hist[dst[i]], 1);
}

__device__ __forceinline__ int wscan_incl32(int x, int lane) {
#pragma unroll
    for (int o = 1; o < 32; o <<= 1) {
        int y = __shfl_up_sync(0xffffffffu, x, o);
        if (lane >= o) x += y;
    }
    return x;
}

// ---- mega-kernel: blocks 0..195 = lookback scan + hist reset + fused hx
//      blocks 196..391 = weight prep + gstart --------------------------------
__global__ void k_scanall(const int* __restrict__ batch,
                          const float* __restrict__ x, const float* __restrict__ cw,
                          const float* __restrict__ W1, const float* __restrict__ W2) {
    int tid = threadIdx.x, bid = blockIdx.x;
    if (bid < NBLK) {
        __shared__ int wsum[8];
        __shared__ int sexc;
        int lane = tid & 31, wid = tid >> 5;
        int i = bid * 256 + tid;
        int v = (i < NN) ? g_hist[i] : 0;
        int incl = wscan_incl32(v, lane);
        if (lane == 31) wsum[wid] = incl;
        __syncthreads();
        if (tid < 8) {
            int b = wsum[tid];
#pragma unroll
            for (int o = 1; o < 8; o <<= 1) {
                int y = __shfl_up_sync(0xffu, b, o);
                if (tid >= o) b += y;
            }
            wsum[tid] = b;
        }
        __syncthreads();
        int wbase = (wid > 0) ? wsum[wid - 1] : 0;
        int total = wsum[7];
        if (tid == 0) {
            if (bid == 0) {
                g_blk_pref[0] = total;
                __threadfence();
                g_blk_flag[0] = 2;
                sexc = 0;
            } else {
                g_blk_agg[bid] = total;
                __threadfence();
                g_blk_flag[bid] = 1;
            }
        }
        if (bid > 0 && wid == 0) {
            int run = 0;
            int p = bid - 1;
            while (true) {
                int idx = p - lane;
                int f = 0, a = 0;
                if (idx >= 0) {
                    while ((f = g_blk_flag[idx]) == 0) {}
                    __threadfence();
                    a = (f == 2) ? g_blk_pref[idx] : g_blk_agg[idx];
                }
                unsigned pm = __ballot_sync(0xffffffffu, idx >= 0 && f == 2);
                if (pm) {
                    int stop = __ffs(pm) - 1;
                    int take = (idx >= 0 && lane <= stop) ? a : 0;
#pragma unroll
                    for (int o = 16; o > 0; o >>= 1) take += __shfl_xor_sync(0xffffffffu, take, o);
                    run += take;
                    break;
                } else {
                    int take = (idx >= 0) ? a : 0;
#pragma unroll
                    for (int o = 16; o > 0; o >>= 1) take += __shfl_xor_sync(0xffffffffu, take, o);
                    run += take;
                    p -= 32;
                }
            }
            if (lane == 0) {
                sexc = run;
                g_blk_pref[bid] = run + total;
                __threadfence();
                g_blk_flag[bid] = 2;
            }
        }
        __syncthreads();
        if (i < NN) {
            g_rowptr[i] = sexc + wbase + incl - v;
            g_dinv[i] = rsqrtf((float)(v + 1));
            g_hist[i] = 0;  // restore invariant for next run
        }
        __syncthreads();
        // fused hx for this block's 256 nodes
        int n0 = bid * 256;
        for (int j = tid; j < 256 * 32; j += 256) {
            int n = n0 + (j >> 5);
            if (n >= NN) break;
            int p = j & 31;
            float a0 = 0.f, a1 = 0.f;
#pragma unroll
            for (int f = 0; f < 5; f++) {
                float xv = x[n * 5 + f];
                a0 += xv * cw[f * 64 + 2 * p];
                a1 += xv * cw[f * 64 + 2 * p + 1];
            }
            float dn = g_dinv[n];
            g_hx16[n * 32 + p] = __floats2half2_rn(a0 * dn, a1 * dn);
        }
    } else {
        int i = (bid - NBLK) * 256 + tid;
        if (i < 3 * 8192) {
            int l = i >> 13, r = i & 8191;
            int o = r >> 6, k = r & 63;
            g_W1T[i] = __float2half(W1[l * 8192 + k * 128 + o]);
        } else if (i < 6 * 8192) {
            int t = i - 3 * 8192;
            int l = t >> 13, r = t & 8191;
            int n = r >> 7, k = r & 127;
            g_W2T[t] = __float2half(W2[l * 8192 + k * 64 + n]);
        }
        if (i < NN) {
            int b = batch[i];
            int prev = (i == 0) ? -1 : batch[i - 1];
            for (int g = prev + 1; g <= b; g++) g_gstart[g] = i;
            if (i == NN - 1) {
                for (int g = b + 1; g <= GG; g++) g_gstart[g] = NN;
            }
        }
    }
}

// scatter consumes rowptr; stores src<<5; resets lookback flags
__global__ void k_scatter(const int* __restrict__ src, const int* __restrict__ dst) {
    int i = blockIdx.x * blockDim.x + threadIdx.x;
    if (i < NBLK) g_blk_flag[i] = 0;
    if (i < EE) {
        int d = dst[i];
        int pos = atomicAdd(&g_rowptr[d], 1);
        g_colsrc[pos] = src[i] << 5;
    }
}

// ---- GCNConv aggregate + BN + ReLU + fused layer-0 LN+PReLU -----------------
#define GEDGE(S) { float2 _f = __half22float2(g_hx16[(S) + l]); a0 += _f.x; a1 += _f.y; }
__global__ void k_gcn(const float* __restrict__ cb, const float* __restrict__ bg,
                      const float* __restrict__ bb, const float* __restrict__ lg,
                      const float* __restrict__ lb, const float* __restrict__ pa) {
    int tid = threadIdx.x;
    int n = blockIdx.x * 8 + (tid >> 5);
    int l = tid & 31;
    if (n >= NN) return;
    int b = (n == 0) ? 0 : g_rowptr[n - 1];
    int e = g_rowptr[n];
    float a0 = 0.f, a1 = 0.f;
    int i = b;
    for (; i < e && (i & 3); i++) GEDGE(g_colsrc[i]);
    for (; i + 8 <= e; i += 8) {
        int4 A = *(const int4*)&g_colsrc[i];
        int4 B = *(const int4*)&g_colsrc[i + 4];
        GEDGE(A.x); GEDGE(A.y); GEDGE(A.z); GEDGE(A.w);
        GEDGE(B.x); GEDGE(B.y); GEDGE(B.z); GEDGE(B.w);
    }
    for (; i + 4 <= e; i += 4) {
        int4 A = *(const int4*)&g_colsrc[i];
        GEDGE(A.x); GEDGE(A.y); GEDGE(A.z); GEDGE(A.w);
    }
    for (; i < e; i++) GEDGE(g_colsrc[i]);
    float2 hx = __half22float2(g_hx16[n * 32 + l]);
    float dn = g_dinv[n];
    const float BNS = rsqrtf(1.f + 1e-5f);
    float v0 = (a0 + hx.x) * dn + cb[2 * l];
    float v1 = (a1 + hx.y) * dn + cb[2 * l + 1];
    v0 = fmaxf(v0 * (bg[2 * l] * BNS) + bb[2 * l], 0.f);
    v1 = fmaxf(v1 * (bg[2 * l + 1] * BNS) + bb[2 * l + 1], 0.f);
    float2 o; o.x = v0; o.y = v1;
    *reinterpret_cast<float2*>(&g_h[n * 64 + 2 * l]) = o;
    g_x16[n * 128 + l] = __floats2half2_rn(v0, v1);
    float s = v0 + v1;
    float q = v0 * v0 + v1 * v1;
#pragma unroll
    for (int off = 16; off > 0; off >>= 1) {
        s += __shfl_xor_sync(0xffffffffu, s, off);
        q += __shfl_xor_sync(0xffffffffu, q, off);
    }
    float mu = s * (1.f / 64.f);
    float var = q * (1.f / 64.f) - mu * mu;
    float rs = rsqrtf(var + 1e-5f);
    float y0 = (v0 - mu) * rs * lg[2 * l] + lb[2 * l];
    y0 = (y0 >= 0.f) ? y0 : pa[2 * l] * y0;
    float y1 = (v1 - mu) * rs * lg[2 * l + 1] + lb[2 * l + 1];
    y1 = (y1 >= 0.f) ? y1 : pa[2 * l + 1] * y1;
    g_u16[n * 32 + l] = __floats2half2_rn(y0, y1);
}

// ---------------- LayerNorm + PReLU (layers 1,2): h -> u16 only --------------
__global__ void k_ln(const float* __restrict__ g, const float* __restrict__ b,
                     const float* __restrict__ a) {
    int tid = threadIdx.x;
    int n = blockIdx.x * 8 + (tid >> 5);
    int l = tid & 31;
    if (n >= NN) return;
    float2 v = *reinterpret_cast<const float2*>(&g_h[n * 64 + 2 * l]);
    float s = v.x + v.y;
    float q = v.x * v.x + v.y * v.y;
#pragma unroll
    for (int off = 16; off > 0; off >>= 1) {
        s += __shfl_xor_sync(0xffffffffu, s, off);
        q += __shfl_xor_sync(0xffffffffu, q, off);
    }
    float mu = s * (1.f / 64.f);
    float var = q * (1.f / 64.f) - mu * mu;
    float rs = rsqrtf(var + 1e-5f);
    float y0 = (v.x - mu) * rs * g[2 * l] + b[2 * l];
    y0 = (y0 >= 0.f) ? y0 : a[2 * l] * y0;
    float y1 = (v.y - mu) * rs * g[2 * l + 1] + b[2 * l + 1];
    y1 = (y1 >= 0.f) ? y1 : a[2 * l + 1] * y1;
    g_u16[n * 32 + l] = __floats2half2_rn(y0, y1);
}

// ---------------- GENConv softmax aggregation (no eps, ex2) ------------------
#define XEDGE(S) { \
    float2 _f = __half22float2(g_u16[(S) + l]); \
    float _v0 = fmaxf(_f.x, 0.f), _v1 = fmaxf(_f.y, 0.f); \
    float _e0 = ex2f(_v0 * t2), _e1 = ex2f(_v1 * t2); \
    s0 += _e0; s1 += _e1; ac0 += _v0 * _e0; ac1 += _v1 * _e1; }
__global__ void k_gen(const float* __restrict__ gen_t, int layer) {
    int tid = threadIdx.x;
    int n = blockIdx.x * 8 + (tid >> 5);
    int l = tid & 31;
    if (n >= NN) return;
    float t2 = __ldg(&gen_t[layer]) * 1.4426950408889634f;
    int b = (n == 0) ? 0 : g_rowptr[n - 1];
    int e = g_rowptr[n];
    float s0 = 0.f, s1 = 0.f, ac0 = 0.f, ac1 = 0.f;
    int i = b;
    for (; i < e && (i & 3); i++) XEDGE(g_colsrc[i]);
    for (; i + 8 <= e; i += 8) {
        int4 A = *(const int4*)&g_colsrc[i];
        int4 B = *(const int4*)&g_colsrc[i + 4];
        XEDGE(A.x); XEDGE(A.y); XEDGE(A.z); XEDGE(A.w);
        XEDGE(B.x); XEDGE(B.y); XEDGE(B.z); XEDGE(B.w);
    }
    for (; i + 4 <= e; i += 4) {
        int4 A = *(const int4*)&g_colsrc[i];
        XEDGE(A.x); XEDGE(A.y); XEDGE(A.z); XEDGE(A.w);
    }
    for (; i < e; i++) XEDGE(g_colsrc[i]);
    float2 u = __half22float2(g_u16[n * 32 + l]);
    float o0 = ((e > b) ? (ac0 / s0) : 0.f) + u.x;
    float o1 = ((e > b) ? (ac1 / s1) : 0.f) + u.y;
    g_agg16[n * 32 + l] = __floats2half2_rn(o0, o1);
}

// ---------------- HMMA fused MLP ---------------------------------------------
#define STA 72    // halves per A row (144B)
#define STW2 136  // halves per W2 row (272B)

__device__ __forceinline__ void ldmx4(uint32_t addr, uint32_t& a0, uint32_t& a1,
                                      uint32_t& a2, uint32_t& a3) {
    asm volatile("ldmatrix.sync.aligned.m8n8.x4.shared.b16 {%0,%1,%2,%3}, [%4];"
                 : "=r"(a0), "=r"(a1), "=r"(a2), "=r"(a3) : "r"(addr));
}
__device__ __forceinline__ void ldmx2(uint32_t addr, uint32_t& b0, uint32_t& b1) {
    asm volatile("ldmatrix.sync.aligned.m8n8.x2.shared.b16 {%0,%1}, [%2];"
                 : "=r"(b0), "=r"(b1) : "r"(addr));
}
__device__ __forceinline__ void mma16816(float* c, const uint32_t* a, const uint32_t* b) {
    asm volatile("mma.sync.aligned.m16n8k16.row.col.f32.f16.f16.f32 "
                 "{%0,%1,%2,%3}, {%4,%5,%6,%7}, {%8,%9}, {%0,%1,%2,%3};"
                 : "+f"(c[0]), "+f"(c[1]), "+f"(c[2]), "+f"(c[3])
                 : "r"(a[0]), "r"(a[1]), "r"(a[2]), "r"(a[3]), "r"(b[0]), "r"(b[1]));
}

__global__ void __launch_bounds__(256)
k_mma(const float* __restrict__ b1, const float* __restrict__ bng,
      const float* __restrict__ bnb, const float* __restrict__ b2, int layer) {
    extern __shared__ char smem[];
    float*  mpar = (float*)smem;              // 128
    float*  apar = mpar + 128;                // 128
    __half* sA   = (__half*)(apar + 128);     // 128*STA
    __half* sW1  = sA + 128 * STA;            // 128*STA
    __half* sW2  = sW1 + 128 * STA;           // 64*STW2
    int tid = threadIdx.x;
    int n0 = blockIdx.x * 128;

    if (tid < 128) {
        const float BNS = rsqrtf(1.f + 1e-5f);
        float m = __ldg(&bng[tid]) * BNS;
        mpar[tid] = m;
        apar[tid] = __ldg(&b1[tid]) * m + __ldg(&bnb[tid]);
    }
    for (int i = tid; i < 128 * 32; i += 256) {
        int r = i >> 5, p = i & 31;
        int n = n0 + r;
        __half2 v = (n < NN) ? g_agg16[n * 32 + p] : __floats2half2_rn(0.f, 0.f);
        *(__half2*)&sA[r * STA + 2 * p] = v;
    }
    const __half* w1p = g_W1T + layer * 8192;
    for (int i = tid; i < 128 * 32; i += 256) {
        int r = i >> 5, p = i & 31;
        *(__half2*)&sW1[r * STA + 2 * p] = *(const __half2*)&w1p[r * 64 + 2 * p];
    }
    const __half* w2p = g_W2T + layer * 8192;
    for (int i = tid; i < 64 * 64; i += 256) {
        int r = i >> 6, p = i & 63;
        *(__half2*)&sW2[r * STW2 + 2 * p] = *(const __half2*)&w2p[r * 128 + 2 * p];
    }
    __syncthreads();

    int wid = tid >> 5, lane = tid & 31;
    int m0 = wid * 16;

    float c[16][4];
#pragma unroll
    for (int nt = 0; nt < 16; nt++)
#pragma unroll
        for (int q = 0; q < 4; q++) c[nt][q] = 0.f;

    int arow = m0 + (lane & 7) + ((lane >> 3) & 1) * 8;
    int acolbase = (lane >> 4) * 8;
    int brow = (lane & 7);
    int bcolbase = ((lane >> 3) & 1) * 8;
#pragma unroll
    for (int kt = 0; kt < 4; kt++) {
        uint32_t a[4];
        ldmx4(smem_u32(&sA[arow * STA + kt * 16 + acolbase]), a[0], a[1], a[2], a[3]);
#pragma unroll
        for (int nt = 0; nt < 16; nt++) {
            uint32_t b[2];
            ldmx2(smem_u32(&sW1[(nt * 8 + brow) * STA + kt * 16 + bcolbase]), b[0], b[1]);
            mma16816(c[nt], a, b);
        }
    }

    int ob = (lane & 3) * 2;
    uint32_t az[8][4];
#pragma unroll
    for (int nt = 0; nt < 16; nt++) {
        int o0 = nt * 8 + ob, o1 = o0 + 1;
        float m0f = mpar[o0], m1f = mpar[o1];
        float a0f = apar[o0], a1f = apar[o1];
        float z0 = fmaxf(c[nt][0] * m0f + a0f, 0.f);
        float z1 = fmaxf(c[nt][1] * m1f + a1f, 0.f);
        float z2 = fmaxf(c[nt][2] * m0f + a0f, 0.f);
        float z3 = fmaxf(c[nt][3] * m1f + a1f, 0.f);
        __half2 p01 = __floats2half2_rn(z0, z1);
        __half2 p23 = __floats2half2_rn(z2, z3);
        az[nt >> 1][(nt & 1) * 2 + 0] = *(uint32_t*)&p01;
        az[nt >> 1][(nt & 1) * 2 + 1] = *(uint32_t*)&p23;
    }

    float d[8][4];
#pragma unroll
    for (int nt = 0; nt < 8; nt++)
#pragma unroll
        for (int q = 0; q < 4; q++) d[nt][q] = 0.f;
#pragma unroll
    for (int kt = 0; kt < 8; kt++) {
#pragma unroll
        for (int nt = 0; nt < 8; nt++) {
            uint32_t b[2];
            ldmx2(smem_u32(&sW2[(nt * 8 + brow) * STW2 + kt * 16 + bcolbase]), b[0], b[1]);
            mma16816(d[nt], az[kt], b);
        }
    }

    int r0 = n0 + m0 + (lane >> 2);
    int r1 = r0 + 8;
    int xoff = (layer + 1) * 32;
#pragma unroll
    for (int nt = 0; nt < 8; nt++) {
        int o0 = nt * 8 + ob;
        float bb0 = __ldg(&b2[o0]);
        float bb1 = __ldg(&b2[o0 + 1]);
        if (r0 < NN) {
            float2 hv = *(float2*)&g_h[r0 * 64 + o0];
            float2 nh;
            nh.x = hv.x + d[nt][0] + bb0;
            nh.y = hv.y + d[nt][1] + bb1;
            *(float2*)&g_h[r0 * 64 + o0] = nh;
            g_x16[r0 * 128 + xoff + (o0 >> 1)] = __floats2half2_rn(nh.x, nh.y);
        }
        if (r1 < NN) {
            float2 hv = *(float2*)&g_h[r1 * 64 + o0];
            float2 nh;
            nh.x = hv.x + d[nt][2] + bb0;
            nh.y = hv.y + d[nt][3] + bb1;
            *(float2*)&g_h[r1 * 64 + o0] = nh;
            g_x16[r1 * 128 + xoff + (o0 >> 1)] = __floats2half2_rn(nh.x, nh.y);
        }
    }
}
#define MMA_SMEM (256 * 4 + (128 * STA + 128 * STA + 64 * STW2) * 2)

// ---------------- fused pooling + readout MLP (512 thr, fp16 xcat) -----------
__global__ void k_poolread(const float* __restrict__ W1, const float* __restrict__ b1,
                           const float* __restrict__ W2, const float* __restrict__ b2,
                           const float* __restrict__ Wo, const float* __restrict__ bo,
                           float* __restrict__ out) {
    __shared__ float ss0[512], ss1[512], sm0[512], sm1[512];
    __shared__ float p[512];
    __shared__ float q1[128];
    __shared__ float q2[64];
    int g = blockIdx.x;
    int tid = threadIdx.x;        // 512
    int pc = tid & 127;
    int q4 = tid >> 7;
    int beg = g_gstart[g], end = g_gstart[g + 1];
    float s0 = 0.f, s1 = 0.f, m0 = -INFINITY, m1 = -INFINITY;
    for (int n = beg + q4; n < end; n += 4) {
        float2 v = __half22float2(g_x16[n * 128 + pc]);
        s0 += v.x; s1 += v.y;
        m0 = fmaxf(m0, v.x); m1 = fmaxf(m1, v.y);
    }
    ss0[tid] = s0; ss1[tid] = s1; sm0[tid] = m0; sm1[tid] = m1;
    __syncthreads();
    if (tid < 128) {
        float S0 = ss0[tid] + ss0[tid + 128] + ss0[tid + 256] + ss0[tid + 384];
        float S1 = ss1[tid] + ss1[tid + 128] + ss1[tid + 256] + ss1[tid + 384];
        float M0 = fmaxf(fmaxf(sm0[tid], sm0[tid + 128]), fmaxf(sm0[tid + 256], sm0[tid + 384]));
        float M1 = fmaxf(fmaxf(sm1[tid], sm1[tid + 128]), fmaxf(sm1[tid + 256], sm1[tid + 384]));
        float cnt = fmaxf((float)(end - beg), 1.f);
        p[2 * tid] = S0 / cnt;
        p[2 * tid + 1] = S1 / cnt;
        p[256 + 2 * tid] = (end > beg) ? M0 : 0.f;
        p[256 + 2 * tid + 1] = (end > beg) ? M1 : 0.f;
    }
    __syncthreads();
    if (tid < 128) {
        float a = b1[tid];
        for (int k = 0; k < 512; k++) a += p[k] * W1[k * 128 + tid];
        q1[tid] = fmaxf(a, 0.f);
    }
    __syncthreads();
    if (tid < 64) {
        float a = b2[tid];
        for (int k = 0; k < 128; k++) a += q1[k] * W2[k * 64 + tid];
        q2[tid] = fmaxf(a, 0.f);
    }
    __syncthreads();
    if (tid < 32) {
        float s = q2[tid] * Wo[tid] + q2[tid + 32] * Wo[tid + 32];
#pragma unroll
        for (int off = 16; off > 0; off >>= 1) s += __shfl_xor_sync(0xffffffffu, s, off);
        if (tid == 0) out[g] = s + bo[0];
    }
}

// ---------------- launch -----------------------------------------------------
extern "C" void kernel_launch(void* const* d_in, const int* in_sizes, int n_in,
                              void* d_out, int out_size) {
    const float* x        = (const float*)d_in[0];
    const int*   ei       = (const int*)d_in[1];
    const int*   batch    = (const int*)d_in[2];
    const float* conv1_W  = (const float*)d_in[3];
    const float* conv1_b  = (const float*)d_in[4];
    const float* bn1_g    = (const float*)d_in[5];
    const float* bn1_b    = (const float*)d_in[6];
    const float* ln_g     = (const float*)d_in[7];
    const float* ln_b     = (const float*)d_in[8];
    const float* prelu_a  = (const float*)d_in[9];
    const float* gen_t    = (const float*)d_in[10];
    const float* mlp_W1   = (const float*)d_in[11];
    const float* mlp_b1   = (const float*)d_in[12];
    const float* mlp_bn_g = (const float*)d_in[13];
    const float* mlp_bn_b = (const float*)d_in[14];
    const float* mlp_W2   = (const float*)d_in[15];
    const float* mlp_b2   = (const float*)d_in[16];
    const float* lin1_W   = (const float*)d_in[17];
    const float* lin1_b   = (const float*)d_in[18];
    const float* lin2_W   = (const float*)d_in[19];
    const float* lin2_b   = (const float*)d_in[20];
    const float* out_W    = (const float*)d_in[21];
    const float* out_b    = (const float*)d_in[22];
    float* out = (float*)d_out;

    const int* src = ei;
    const int* dst = ei + EE;

    static int smem_set = 0;
    if (!smem_set) {
        cudaFuncSetAttribute(k_mma, cudaFuncAttributeMaxDynamicSharedMemorySize, MMA_SMEM);
        smem_set = 1;
    }

    k_hist<<<(EE + 255) / 256, 256>>>(dst);
    k_scanall<<<2 * NBLK, 256>>>(batch, x, conv1_W, mlp_W1, mlp_W2);
    k_scatter<<<(EE + 255) / 256, 256>>>(src, dst);
    k_gcn<<<(NN + 7) / 8, 256>>>(conv1_b, bn1_g, bn1_b, ln_g, ln_b, prelu_a);

    for (int i = 0; i < 3; i++) {
        if (i > 0) k_ln<<<(NN + 7) / 8, 256>>>(ln_g + i * 64, ln_b + i * 64, prelu_a + i * 64);
        k_gen<<<(NN + 7) / 8, 256>>>(gen_t, i);
        k_mma<<<(NN + 127) / 128, 256, MMA_SMEM>>>(mlp_b1 + i * 128, mlp_bn_g + i * 128,
                                                   mlp_bn_b + i * 128, mlp_b2 + i * 64, i);
    }

    k_poolread<<<GG, 512>>>(lin1_W, lin1_b, lin2_W, lin2_b, out_W, out_b, out);
}